// round 8
// baseline (speedup 1.0000x reference)
#include <cuda_runtime.h>
#include <math_constants.h>

// Problem constants
#define KS     7
#define HALF   3
#define B_DIM  32
#define C_DIM  64
#define L_DIM  4096
#define I_DIM  (L_DIM / 2)        // 2048 outputs per row
#define ROWS_PER_BLK 16
#define NBLK   (B_DIM * C_DIM / ROWS_PER_BLK)   // 128
#define NTHREADS 512

// Block table range: k in [s0, s0 + 15 + 2*2047] -> 4110 entries
#define E_N   4110
// f window: f_flat[s0-3 .. s0+4112] -> 4116 floats
#define F_N   4116

// Padded smem index: stride-8 gather reads become conflict-free
// (bank(m) = (8*(m%4) + m/4) % 32, all 32 distinct).
#define PD(e) ((e) + ((e) >> 5))

// ---------------------------------------------------------------------------
// Single kernel, no inter-block deps. Block q owns rows 16q..16q+15 (same b:
// 16 | 64, so b = q>>2, c_base = (q&3)*16, s = s0 + rr with s0 = b + c_base).
// out[row, i] = dil(s + 2i); valid tap z of dil(k) = f_flat[k+z] + h[c',z],
// h[c',z] = -(z^2)/(4*t[c']), c' = k>>12, validity 0 <= (k&4095)+z < L.
// ---------------------------------------------------------------------------
__global__ void __launch_bounds__(NTHREADS) pp_kernel(
        const float* __restrict__ f,
        const float* __restrict__ t,
        float4* __restrict__ out) {
    __shared__ float fwin[F_N];
    __shared__ float dwin[PD(E_N - 1) + 16];

    const int tid = threadIdx.x;
    const int q   = blockIdx.x;
    const int s0  = (q >> 2) + ((q & 3) << 4);   // b + c_base, <= 79

    // ---- Stage f window (coalesced; low-edge guard only) ----
    #pragma unroll
    for (int x = tid; x < F_N; x += NTHREADS) {
        int g = s0 - 3 + x;                      // max 79-3+4115 = 4191 < 8192
        fwin[x] = (g >= 0) ? __ldg(&f[g]) : 0.0f;
    }

    // ---- Hoisted h values (same rounding as reference: -(z^2)/(4t)) ----
    float d0 = 4.0f * __ldg(&t[0]);
    float d1 = 4.0f * __ldg(&t[1]);
    float h1_0 = -1.0f / d0, h4_0 = -4.0f / d0, h9_0 = -9.0f / d0;
    float h1_1 = -1.0f / d1, h4_1 = -4.0f / d1, h9_1 = -9.0f / d1;

    __syncthreads();

    // ---- Dilation window: dil(s0 + e), e in [0, E_N) ----
    #pragma unroll
    for (int e = tid; e < E_N; e += NTHREADS) {
        int k  = s0 + e;
        int l0 = k & (L_DIM - 1);
        bool c1 = (k >> 12) != 0;
        float h1 = c1 ? h1_1 : h1_0;
        float h4 = c1 ? h4_1 : h4_0;
        float h9 = c1 ? h9_1 : h9_0;

        const float* w = &fwin[e + HALF];        // w[z] = f_flat[k+z]
        float m = w[0];                                          // z = 0
        m = fmaxf(m, (l0 >= 1)         ? w[-1] + h1 : -CUDART_INF_F);
        m = fmaxf(m, (l0 < L_DIM - 1)  ? w[ 1] + h1 : -CUDART_INF_F);
        m = fmaxf(m, (l0 >= 2)         ? w[-2] + h4 : -CUDART_INF_F);
        m = fmaxf(m, (l0 < L_DIM - 2)  ? w[ 2] + h4 : -CUDART_INF_F);
        m = fmaxf(m, (l0 >= 3)         ? w[-3] + h9 : -CUDART_INF_F);
        m = fmaxf(m, (l0 < L_DIM - 3)  ? w[ 3] + h9 : -CUDART_INF_F);

        dwin[PD(e)] = m;
    }

    __syncthreads();

    // ---- Emit 16 rows x 512 float4 (8192 float4/block, 16 per thread) ----
    float4* __restrict__ oblk = out + (q << 4) * (I_DIM / 4);
    #pragma unroll
    for (int w = 0; w < 16; ++w) {
        int u  = w * NTHREADS + tid;             // 0..8191
        int rr = u >> 9;                         // local row 0..15
        int i4 = u & (I_DIM / 4 - 1);            // float4 index in row
        int e0 = rr + (i4 << 3);                 // element e for i = 4*i4
        float4 r;
        r.x = dwin[PD(e0)];
        r.y = dwin[PD(e0 + 2)];
        r.z = dwin[PD(e0 + 4)];
        r.w = dwin[PD(e0 + 6)];
        oblk[rr * (I_DIM / 4) + i4] = r;
    }
}

extern "C" void kernel_launch(void* const* d_in, const int* in_sizes, int n_in,
                              void* d_out, int out_size) {
    const float* f = (const float*)d_in[0];   // [32, 64, 4096] float32
    const float* t = (const float*)d_in[1];   // [64] float32
    float4* out = (float4*)d_out;             // [32, 64, 2048] float32

    pp_kernel<<<NBLK, NTHREADS>>>(f, t, out);
}

// round 9
// speedup vs baseline: 1.4048x; 1.4048x over previous
#include <cuda_runtime.h>
#include <math_constants.h>

// Problem constants
#define KS     7
#define HALF   3
#define B_DIM  32
#define C_DIM  64
#define L_DIM  4096
#define I_DIM  (L_DIM / 2)        // 2048 outputs per row
#define ROWS_PER_BLK 8
#define NBLK   (B_DIM * C_DIM / ROWS_PER_BLK)   // 256
#define NTHREADS 512

// Block table range: k in [s0, s0 + 7 + 2*2047] -> 4102 entries
#define E_N   4102
// f window: f_flat[s0-3 .. s0+4104] -> 4108 floats
#define F_N   4108

// Padded smem index: stride-8 gather reads hit 32 distinct banks.
#define PD(e) ((e) + ((e) >> 5))

// ---------------------------------------------------------------------------
// Single kernel, no inter-block deps. Block q owns rows 8q..8q+7 (same b:
// b = q>>3, c_base = (q&7)*8, s = s0 + rr, s0 = b + c_base <= 87).
// out[row, i] = dil(s + 2i); valid tap z of dil(k) = f_flat[k+z] + h[c',z],
// h[c',z] = -(z^2)/(4*t[c']), c' = k>>12, validity 0 <= (k&4095)+z < L.
// ---------------------------------------------------------------------------
__global__ void __launch_bounds__(NTHREADS) pp_kernel(
        const float* __restrict__ f,
        const float* __restrict__ t,
        float4* __restrict__ out) {
    __shared__ float fwin[F_N];
    __shared__ float dwin[PD(E_N - 1) + 16];

    const int tid = threadIdx.x;
    const int q   = blockIdx.x;
    const int s0  = (q >> 3) + ((q & 7) << 3);   // b + c_base, <= 87

    // ---- Stage f window (coalesced; low-edge guard only) ----
    #pragma unroll
    for (int x = tid; x < F_N; x += NTHREADS) {
        int g = s0 - 3 + x;                      // max 87-3+4107 = 4191 < 8192
        fwin[x] = (g >= 0) ? __ldg(&f[g]) : 0.0f;
    }

    // ---- Hoisted h values (same rounding as reference: -(z^2)/(4t)) ----
    float d0 = 4.0f * __ldg(&t[0]);
    float d1 = 4.0f * __ldg(&t[1]);
    float h1_0 = -1.0f / d0, h4_0 = -4.0f / d0, h9_0 = -9.0f / d0;
    float h1_1 = -1.0f / d1, h4_1 = -4.0f / d1, h9_1 = -9.0f / d1;

    __syncthreads();

    // ---- Dilation window: dil(s0 + e), e in [0, E_N) ----
    #pragma unroll
    for (int e = tid; e < E_N; e += NTHREADS) {
        int k  = s0 + e;
        int l0 = k & (L_DIM - 1);
        bool c1 = (k >> 12) != 0;
        float h1 = c1 ? h1_1 : h1_0;
        float h4 = c1 ? h4_1 : h4_0;
        float h9 = c1 ? h9_1 : h9_0;

        const float* w = &fwin[e + HALF];        // w[z] = f_flat[k+z]
        float m = w[0];                                          // z = 0
        m = fmaxf(m, (l0 >= 1)         ? w[-1] + h1 : -CUDART_INF_F);
        m = fmaxf(m, (l0 < L_DIM - 1)  ? w[ 1] + h1 : -CUDART_INF_F);
        m = fmaxf(m, (l0 >= 2)         ? w[-2] + h4 : -CUDART_INF_F);
        m = fmaxf(m, (l0 < L_DIM - 2)  ? w[ 2] + h4 : -CUDART_INF_F);
        m = fmaxf(m, (l0 >= 3)         ? w[-3] + h9 : -CUDART_INF_F);
        m = fmaxf(m, (l0 < L_DIM - 3)  ? w[ 3] + h9 : -CUDART_INF_F);

        dwin[PD(e)] = m;
    }

    __syncthreads();

    // ---- Emit 8 rows x 512 float4 (4096 float4/block, 8 per thread) ----
    float4* __restrict__ oblk = out + (q << 3) * (I_DIM / 4);
    #pragma unroll
    for (int w = 0; w < 8; ++w) {
        int u  = w * NTHREADS + tid;             // 0..4095
        int rr = u >> 9;                         // local row 0..7
        int i4 = u & (I_DIM / 4 - 1);            // float4 index in row
        int e0 = rr + (i4 << 3);                 // element e for i = 4*i4
        float4 r;
        r.x = dwin[PD(e0)];
        r.y = dwin[PD(e0 + 2)];
        r.z = dwin[PD(e0 + 4)];
        r.w = dwin[PD(e0 + 6)];
        oblk[rr * (I_DIM / 4) + i4] = r;
    }
}

extern "C" void kernel_launch(void* const* d_in, const int* in_sizes, int n_in,
                              void* d_out, int out_size) {
    const float* f = (const float*)d_in[0];   // [32, 64, 4096] float32
    const float* t = (const float*)d_in[1];   // [64] float32
    float4* out = (float4*)d_out;             // [32, 64, 2048] float32

    pp_kernel<<<NBLK, NTHREADS>>>(f, t, out);
}

// round 11
// speedup vs baseline: 1.6738x; 1.1915x over previous
#include <cuda_runtime.h>
#include <math_constants.h>

// Problem constants
#define KS     7
#define HALF   3
#define B_DIM  32
#define C_DIM  64
#define L_DIM  4096
#define I_DIM  (L_DIM / 2)        // 2048 outputs per row
#define ROWS_PER_BLK 16
#define NBLK   (B_DIM * C_DIM / ROWS_PER_BLK)   // 128
#define NTHREADS 512

// Block table range: k in [s0, s0 + 15 + 2*2047] -> 4110 entries
#define E_N    4110
// f window: f_flat[s0-3 .. s0+4112] -> 4116 floats
#define F_N    4116
// 8-entry chunks
#define NCHUNK ((E_N + 7) / 8)    // 514

// Padded smem index: stride-8 gather reads hit 32 distinct banks.
#define PD(e) ((e) + ((e) >> 5))

// ---------------------------------------------------------------------------
// Single kernel, no inter-block deps. Block q owns rows 16q..16q+15
// (b = q>>2, c_base = (q&3)*16, s0 = b + c_base <= 79).
// out[row, i] = dil(s + 2i); valid tap z of dil(k) = f_flat[k+z] + h[c',z],
// h[c',z] = -(z^2)/(4*t[c']), c' = k>>12, validity 0 <= (k&4095)+z < L.
// ---------------------------------------------------------------------------
__global__ void __launch_bounds__(NTHREADS) pp_kernel(
        const float* __restrict__ f,
        const float* __restrict__ t,
        float4* __restrict__ out) {
    __shared__ __align__(16) float fwin[F_N];
    __shared__ float dwin[PD(E_N - 1) + 16];

    const int tid = threadIdx.x;
    const int q   = blockIdx.x;
    const int s0  = (q >> 2) + ((q & 3) << 4);   // b + c_base, <= 79

    // ---- Stage f window (coalesced; low-edge guard only) ----
    #pragma unroll
    for (int x = tid; x < F_N; x += NTHREADS) {
        int g = s0 - 3 + x;                      // max 79-3+4115 = 4191 < 2^13
        fwin[x] = (g >= 0) ? __ldg(&f[g]) : 0.0f;
    }

    // ---- Hoisted h values (same rounding as reference: -(z^2)/(4t)) ----
    const float d0 = 4.0f * __ldg(&t[0]);
    const float d1 = 4.0f * __ldg(&t[1]);
    const float h1c[2] = { -1.0f / d0, -1.0f / d1 };
    const float h4c[2] = { -4.0f / d0, -4.0f / d1 };
    const float h9c[2] = { -9.0f / d0, -9.0f / d1 };

    __syncthreads();

    // ---- Dilation window: 8-entry chunks, interior fast path ----
    for (int ch = tid; ch < NCHUNK; ch += NTHREADS) {
        const int e0 = ch << 3;
        const int k0 = s0 + e0;
        const int l0f = k0 & (L_DIM - 1);
        const bool interior = (l0f >= HALF) && (l0f <= L_DIM - 4 - 7)
                              && (e0 + 7 < E_N);

        if (interior) {
            const int c1 = (k0 >> 12) & 1;
            const float h1 = h1c[c1], h4 = h4c[c1], h9 = h9c[c1];
            // v[x] = fwin[e0 + x], x = 0..13 ; entry j taps v[j..j+6]
            float v[14];
            float4 a = *reinterpret_cast<const float4*>(&fwin[e0]);
            float4 b = *reinterpret_cast<const float4*>(&fwin[e0 + 4]);
            float4 c = *reinterpret_cast<const float4*>(&fwin[e0 + 8]);
            float2 d = *reinterpret_cast<const float2*>(&fwin[e0 + 12]);
            v[0]=a.x; v[1]=a.y; v[2]=a.z; v[3]=a.w;
            v[4]=b.x; v[5]=b.y; v[6]=b.z; v[7]=b.w;
            v[8]=c.x; v[9]=c.y; v[10]=c.z; v[11]=c.w;
            v[12]=d.x; v[13]=d.y;
            #pragma unroll
            for (int j = 0; j < 8; ++j) {
                float mx1 = fmaxf(v[j + 2], v[j + 4]);
                float mx4 = fmaxf(v[j + 1], v[j + 5]);
                float mx9 = fmaxf(v[j],     v[j + 6]);
                float m = fmaxf(fmaxf(v[j + 3], mx1 + h1),
                                fmaxf(mx4 + h4, mx9 + h9));
                dwin[PD(e0 + j)] = m;
            }
        } else {
            // Border / tail chunk: fully predicated per entry (rare)
            #pragma unroll
            for (int j = 0; j < 8; ++j) {
                int e = e0 + j;
                if (e >= E_N) break;
                int k  = s0 + e;
                int l0 = k & (L_DIM - 1);
                int c1 = (k >> 12) & 1;
                float h1 = h1c[c1], h4 = h4c[c1], h9 = h9c[c1];
                const float* w = &fwin[e + HALF];
                float m = w[0];
                m = fmaxf(m, (l0 >= 1)        ? w[-1] + h1 : -CUDART_INF_F);
                m = fmaxf(m, (l0 < L_DIM - 1) ? w[ 1] + h1 : -CUDART_INF_F);
                m = fmaxf(m, (l0 >= 2)        ? w[-2] + h4 : -CUDART_INF_F);
                m = fmaxf(m, (l0 < L_DIM - 2) ? w[ 2] + h4 : -CUDART_INF_F);
                m = fmaxf(m, (l0 >= 3)        ? w[-3] + h9 : -CUDART_INF_F);
                m = fmaxf(m, (l0 < L_DIM - 3) ? w[ 3] + h9 : -CUDART_INF_F);
                dwin[PD(e)] = m;
            }
        }
    }

    __syncthreads();

    // ---- Emit 16 rows x 512 float4 (8192 float4/block, 16 per thread) ----
    float4* __restrict__ oblk = out + (q << 4) * (I_DIM / 4);
    #pragma unroll
    for (int w = 0; w < 16; ++w) {
        int u  = w * NTHREADS + tid;             // 0..8191
        int rr = u >> 9;                         // local row 0..15
        int i4 = u & (I_DIM / 4 - 1);            // float4 index in row
        int e0 = rr + (i4 << 3);                 // element e for i = 4*i4
        float4 r;
        r.x = dwin[PD(e0)];
        r.y = dwin[PD(e0 + 2)];
        r.z = dwin[PD(e0 + 4)];
        r.w = dwin[PD(e0 + 6)];
        oblk[rr * (I_DIM / 4) + i4] = r;
    }
}

extern "C" void kernel_launch(void* const* d_in, const int* in_sizes, int n_in,
                              void* d_out, int out_size) {
    const float* f = (const float*)d_in[0];   // [32, 64, 4096] float32
    const float* t = (const float*)d_in[1];   // [64] float32
    float4* out = (float4*)d_out;             // [32, 64, 2048] float32

    pp_kernel<<<NBLK, NTHREADS>>>(f, t, out);
}